// round 3
// baseline (speedup 1.0000x reference)
#include <cuda_runtime.h>

// Problem constants
#define BATCH   256
#define NMAXN   512
#define HDIM    256      // H
#define CDIM    64       // C
#define HIDN    512      // HID
#define TM      32       // candidate rows per CTA tile
#define KK      16       // k-tile staged in smem
#define NTHREADS 512
#define NEGV   (-1000000000.0f)

// Scratch (no allocations allowed)
__device__ float g_base1[BATCH * HIDN];
__device__ float g_scores[BATCH * NMAXN];

// ---- packed f32x2 helpers (sm_103a) ----
__device__ __forceinline__ void ffma2(unsigned long long &d,
                                      unsigned long long a,
                                      unsigned long long b) {
    asm("fma.rn.f32x2 %0, %1, %2, %0;" : "+l"(d) : "l"(a), "l"(b));
}
__device__ __forceinline__ unsigned long long splat2(float x) {
    unsigned long long r;
    asm("mov.b64 %0, {%1, %1};" : "=l"(r) : "f"(x));
    return r;
}
__device__ __forceinline__ float2 unpack2(unsigned long long u) {
    float2 f;
    asm("mov.b64 {%0, %1}, %2;" : "=f"(f.x), "=f"(f.y) : "l"(u));
    return f;
}

// ============================================================================
// Kernel 0: per-batch constant contribution of layer 1
// base1[b][j] = b1[j] + sum_k src[k]*W1[coff+k][j] + sum_k cc[k]*W1[2H+k][j]
// ============================================================================
__global__ void __launch_bounds__(HIDN) base_kernel(
    const float* __restrict__ nodes, const float* __restrict__ cc,
    const float* __restrict__ W1, const float* __restrict__ b1,
    const int* __restrict__ dirns, const int* __restrict__ ncnt)
{
    int b   = blockIdx.x;
    int tid = threadIdx.x;   // 512 threads, one output column each

    __shared__ float s_src[HDIM];
    __shared__ float s_cc[CDIM];

    int si = ncnt[b] - 1;
    if (tid < HDIM) s_src[tid] = nodes[((size_t)b * NMAXN + si) * HDIM + tid];
    if (tid < CDIM) s_cc[tid]  = cc[(size_t)b * CDIM + tid];
    __syncthreads();

    // dirn==1: side_a = cand (W1 rows [0,256) varying) -> const side rows [256,512)
    // dirn==0: const side rows [0,256)
    int coff = (dirns[b] == 1) ? HDIM : 0;

    float acc = b1[tid];
    const float* Wc = W1 + (size_t)coff * HIDN + tid;
#pragma unroll 8
    for (int k = 0; k < HDIM; k++) acc += s_src[k] * Wc[(size_t)k * HIDN];
    const float* Wcc = W1 + (size_t)(2 * HDIM) * HIDN + tid;
#pragma unroll 8
    for (int k = 0; k < CDIM; k++) acc += s_cc[k] * Wcc[(size_t)k * HIDN];

    g_base1[(size_t)b * HIDN + tid] = acc;
}

// ============================================================================
// Kernel 1: fused MLP for a 32-row candidate tile of one batch.
// h1 = relu(cand @ W1var + base1)        (K=256)
// h2 = relu(h1 @ W2 + b2)                (K=512, h2 kept in regs)
// score[r] = h2[r] . W3  (+ b3 at write)
// grid = (16, 256), block = 512, 1 CTA/SM (133 KB dynamic smem)
// Thread tile: 8 rows x 4 cols, f32x2 accumulators.
// tc = tid & 127 -> j0 = tc*4 ;  tr = tid >> 7 -> r0 = tr*8
// ============================================================================
__global__ void __launch_bounds__(NTHREADS, 1) mlp_kernel(
    const float* __restrict__ nodes,
    const float* __restrict__ W1, const float* __restrict__ W2,
    const float* __restrict__ b2, const float* __restrict__ W3,
    const float* __restrict__ b3,
    const int* __restrict__ dirns, const int* __restrict__ ncnt)
{
    extern __shared__ float sm[];
    float* s_cand  = sm;                        // TM*HDIM   = 8192 floats
    float* s_h1    = s_cand + TM * HDIM;        // TM*HIDN   = 16384
    float* s_wt    = s_h1 + TM * HIDN;          // KK*HIDN   = 8192
    float* s_base  = s_wt + KK * HIDN;          // HIDN      = 512
    float* s_score = s_base + HIDN;             // TM        = 32

    int b   = blockIdx.y;
    int d0  = blockIdx.x * TM;
    int tid = threadIdx.x;
    int tc  = tid & 127;
    int tr  = tid >> 7;
    int j0  = tc * 4;
    int r0  = tr * 8;

    // ---- prologue loads ----
    {
        const float4* g4 = (const float4*)(nodes + ((size_t)b * NMAXN + d0) * HDIM);
        float4* c4 = (float4*)s_cand;           // 2048 float4s
#pragma unroll
        for (int i = 0; i < 4; i++) c4[tid + i * NTHREADS] = g4[tid + i * NTHREADS];
    }
    s_base[tid] = g_base1[(size_t)b * HIDN + tid];
    if (tid < TM) s_score[tid] = 0.0f;
    int voff = (dirns[b] == 1) ? 0 : HDIM;      // varying-side W1 row offset

    unsigned long long acc[8][2];
#pragma unroll
    for (int i = 0; i < 8; i++) { acc[i][0] = 0ull; acc[i][1] = 0ull; }

    // ---- layer 1: K = 256 ----
    const float* Wg1 = W1 + (size_t)voff * HIDN;
    for (int kk = 0; kk < HDIM; kk += KK) {
        __syncthreads();
        const float4* wg4 = (const float4*)(Wg1 + (size_t)kk * HIDN);
        float4* wt4 = (float4*)s_wt;            // 2048 float4s
#pragma unroll
        for (int i = 0; i < 4; i++) wt4[tid + i * NTHREADS] = wg4[tid + i * NTHREADS];
        __syncthreads();
#pragma unroll
        for (int k = 0; k < KK; k++) {
            ulonglong2 wv = *(const ulonglong2*)&s_wt[(size_t)k * HIDN + j0];
#pragma unroll
            for (int i = 0; i < 8; i++) {
                unsigned long long a2 = splat2(s_cand[(size_t)(r0 + i) * HDIM + kk + k]);
                ffma2(acc[i][0], a2, wv.x);
                ffma2(acc[i][1], a2, wv.y);
            }
        }
    }

    // epilogue layer 1: + base1, relu, store h1 tile
    {
        float4 bs = *(const float4*)&s_base[j0];
#pragma unroll
        for (int i = 0; i < 8; i++) {
            float2 a0 = unpack2(acc[i][0]);
            float2 a1 = unpack2(acc[i][1]);
            float4 h;
            h.x = fmaxf(a0.x + bs.x, 0.0f);
            h.y = fmaxf(a0.y + bs.y, 0.0f);
            h.z = fmaxf(a1.x + bs.z, 0.0f);
            h.w = fmaxf(a1.y + bs.w, 0.0f);
            *(float4*)&s_h1[(size_t)(r0 + i) * HIDN + j0] = h;
            acc[i][0] = 0ull; acc[i][1] = 0ull;
        }
    }

    // ---- layer 2: K = 512 ----
    for (int kk = 0; kk < HIDN; kk += KK) {
        __syncthreads();   // also guards the h1 writes above on first iter
        const float4* wg4 = (const float4*)(W2 + (size_t)kk * HIDN);
        float4* wt4 = (float4*)s_wt;
#pragma unroll
        for (int i = 0; i < 4; i++) wt4[tid + i * NTHREADS] = wg4[tid + i * NTHREADS];
        __syncthreads();
#pragma unroll
        for (int k = 0; k < KK; k++) {
            ulonglong2 wv = *(const ulonglong2*)&s_wt[(size_t)k * HIDN + j0];
#pragma unroll
            for (int i = 0; i < 8; i++) {
                unsigned long long a2 = splat2(s_h1[(size_t)(r0 + i) * HIDN + kk + k]);
                ffma2(acc[i][0], a2, wv.x);
                ffma2(acc[i][1], a2, wv.y);
            }
        }
    }

    // epilogue layer 2 + layer 3: relu(+b2), dot with W3, reduce per row
    {
        float4 b2v = *(const float4*)&b2[j0];
        float4 w3v = *(const float4*)&W3[j0];
#pragma unroll
        for (int i = 0; i < 8; i++) {
            float2 a0 = unpack2(acc[i][0]);
            float2 a1 = unpack2(acc[i][1]);
            float h0 = fmaxf(a0.x + b2v.x, 0.0f);
            float h1 = fmaxf(a0.y + b2v.y, 0.0f);
            float h2 = fmaxf(a1.x + b2v.z, 0.0f);
            float h3 = fmaxf(a1.y + b2v.w, 0.0f);
            float sc = h0 * w3v.x + h1 * w3v.y + h2 * w3v.z + h3 * w3v.w;
#pragma unroll
            for (int o = 16; o > 0; o >>= 1)
                sc += __shfl_xor_sync(0xffffffffu, sc, o);
            if ((tid & 31) == 0) atomicAdd(&s_score[r0 + i], sc);
        }
    }

    __syncthreads();
    if (tid < TM) {
        int d   = d0 + tid;
        int lim = ncnt[b] - 1;
        float v = (d < lim) ? (s_score[tid] + b3[0]) : NEGV;
        g_scores[(size_t)b * NMAXN + d] = v;   // 16 tiles * 32 = all 512 slots
    }
}

// ============================================================================
// Kernel 2: per-batch log-softmax NLL.  loss = max + log(sum exp) - score[dest]
// ============================================================================
__global__ void __launch_bounds__(NMAXN) loss_kernel(
    const int* __restrict__ dests, float* __restrict__ out)
{
    int b   = blockIdx.x;
    int tid = threadIdx.x;   // 512
    __shared__ float red[NMAXN];

    float v = g_scores[(size_t)b * NMAXN + tid];

    red[tid] = v;
    __syncthreads();
    for (int o = 256; o > 0; o >>= 1) {
        if (tid < o) red[tid] = fmaxf(red[tid], red[tid + o]);
        __syncthreads();
    }
    float mx = red[0];
    __syncthreads();

    red[tid] = expf(v - mx);
    __syncthreads();
    for (int o = 256; o > 0; o >>= 1) {
        if (tid < o) red[tid] = red[tid] + red[tid + o];
        __syncthreads();
    }

    if (tid == 0) {
        float sd = g_scores[(size_t)b * NMAXN + dests[b]];
        out[b] = mx + logf(red[0]) - sd;
    }
}

// ============================================================================
extern "C" void kernel_launch(void* const* d_in, const int* in_sizes, int n_in,
                              void* d_out, int out_size)
{
    const float* nodes = (const float*)d_in[0];
    const float* cc    = (const float*)d_in[1];
    const float* W1    = (const float*)d_in[2];
    const float* b1    = (const float*)d_in[3];
    const float* W2    = (const float*)d_in[4];
    const float* b2    = (const float*)d_in[5];
    const float* W3    = (const float*)d_in[6];
    const float* b3    = (const float*)d_in[7];
    const int* dirns   = (const int*)d_in[8];
    const int* ncnt    = (const int*)d_in[9];
    const int* dests   = (const int*)d_in[10];
    float* out = (float*)d_out;

    base_kernel<<<BATCH, HIDN>>>(nodes, cc, W1, b1, dirns, ncnt);

    size_t smem = (size_t)(TM * HDIM + TM * HIDN + KK * HIDN + HIDN + TM) * sizeof(float);
    cudaFuncSetAttribute(mlp_kernel, cudaFuncAttributeMaxDynamicSharedMemorySize, (int)smem);
    dim3 grid(NMAXN / TM, BATCH);   // 16 x 256
    mlp_kernel<<<grid, NTHREADS, smem>>>(nodes, W1, W2, b2, W3, b3, dirns, ncnt);

    loss_kernel<<<BATCH, NMAXN>>>(dests, out);
}

// round 8
// speedup vs baseline: 1.0004x; 1.0004x over previous
#include <cuda_runtime.h>

// Problem constants
#define BATCH   256
#define NMAXN   512
#define HDIM    256      // H
#define CDIM    64       // C
#define HIDN    512      // HID
#define TM      32       // candidate rows per CTA tile
#define KK      16       // k-tile staged in smem
#define NTHREADS 512
#define NEGV   (-1000000000.0f)

// Scratch (no allocations allowed)
__device__ float g_base1[BATCH * HIDN];
__device__ float g_scores[BATCH * NMAXN];

// ---- packed f32x2 helpers (sm_103a) ----
__device__ __forceinline__ void ffma2(unsigned long long &d,
                                      unsigned long long a,
                                      unsigned long long b) {
    asm("fma.rn.f32x2 %0, %1, %2, %0;" : "+l"(d) : "l"(a), "l"(b));
}
__device__ __forceinline__ unsigned long long splat2(float x) {
    unsigned long long r;
    asm("mov.b64 %0, {%1, %1};" : "=l"(r) : "f"(x));
    return r;
}
__device__ __forceinline__ float2 unpack2(unsigned long long u) {
    float2 f;
    asm("mov.b64 {%0, %1}, %2;" : "=f"(f.x), "=f"(f.y) : "l"(u));
    return f;
}

// ============================================================================
// Kernel 0: per-batch constant contribution of layer 1
// base1[b][j] = b1[j] + sum_k src[k]*W1[coff+k][j] + sum_k cc[k]*W1[2H+k][j]
// ============================================================================
__global__ void __launch_bounds__(HIDN) base_kernel(
    const float* __restrict__ nodes, const float* __restrict__ cc,
    const float* __restrict__ W1, const float* __restrict__ b1,
    const int* __restrict__ dirns, const int* __restrict__ ncnt)
{
    int b   = blockIdx.x;
    int tid = threadIdx.x;   // 512 threads, one output column each

    __shared__ float s_src[HDIM];
    __shared__ float s_cc[CDIM];

    int si = ncnt[b] - 1;
    if (tid < HDIM) s_src[tid] = nodes[((size_t)b * NMAXN + si) * HDIM + tid];
    if (tid < CDIM) s_cc[tid]  = cc[(size_t)b * CDIM + tid];
    __syncthreads();

    // dirn==1: side_a = cand (W1 rows [0,256) varying) -> const side rows [256,512)
    // dirn==0: const side rows [0,256)
    int coff = (dirns[b] == 1) ? HDIM : 0;

    float acc = b1[tid];
    const float* Wc = W1 + (size_t)coff * HIDN + tid;
#pragma unroll 8
    for (int k = 0; k < HDIM; k++) acc += s_src[k] * Wc[(size_t)k * HIDN];
    const float* Wcc = W1 + (size_t)(2 * HDIM) * HIDN + tid;
#pragma unroll 8
    for (int k = 0; k < CDIM; k++) acc += s_cc[k] * Wcc[(size_t)k * HIDN];

    g_base1[(size_t)b * HIDN + tid] = acc;
}

// ============================================================================
// Kernel 1: fused MLP for a 32-row candidate tile of one batch.
// h1 = relu(cand @ W1var + base1)        (K=256)
// h2 = relu(h1 @ W2 + b2)                (K=512, h2 kept in regs)
// score[r] = h2[r] . W3  (+ b3 at write)
// grid = (16, 256), block = 512, 1 CTA/SM (133 KB dynamic smem)
// Thread tile: 8 rows x 4 cols, f32x2 accumulators.
// tc = tid & 127 -> j0 = tc*4 ;  tr = tid >> 7 -> r0 = tr*8
// ============================================================================
__global__ void __launch_bounds__(NTHREADS, 1) mlp_kernel(
    const float* __restrict__ nodes,
    const float* __restrict__ W1, const float* __restrict__ W2,
    const float* __restrict__ b2, const float* __restrict__ W3,
    const float* __restrict__ b3,
    const int* __restrict__ dirns, const int* __restrict__ ncnt)
{
    extern __shared__ float sm[];
    float* s_cand  = sm;                        // TM*HDIM   = 8192 floats
    float* s_h1    = s_cand + TM * HDIM;        // TM*HIDN   = 16384
    float* s_wt    = s_h1 + TM * HIDN;          // KK*HIDN   = 8192
    float* s_base  = s_wt + KK * HIDN;          // HIDN      = 512
    float* s_score = s_base + HIDN;             // TM        = 32

    int b   = blockIdx.y;
    int d0  = blockIdx.x * TM;
    int tid = threadIdx.x;
    int tc  = tid & 127;
    int tr  = tid >> 7;
    int j0  = tc * 4;
    int r0  = tr * 8;

    // ---- prologue loads ----
    {
        const float4* g4 = (const float4*)(nodes + ((size_t)b * NMAXN + d0) * HDIM);
        float4* c4 = (float4*)s_cand;           // 2048 float4s
#pragma unroll
        for (int i = 0; i < 4; i++) c4[tid + i * NTHREADS] = g4[tid + i * NTHREADS];
    }
    s_base[tid] = g_base1[(size_t)b * HIDN + tid];
    if (tid < TM) s_score[tid] = 0.0f;
    int voff = (dirns[b] == 1) ? 0 : HDIM;      // varying-side W1 row offset

    unsigned long long acc[8][2];
#pragma unroll
    for (int i = 0; i < 8; i++) { acc[i][0] = 0ull; acc[i][1] = 0ull; }

    // ---- layer 1: K = 256 ----
    const float* Wg1 = W1 + (size_t)voff * HIDN;
    for (int kk = 0; kk < HDIM; kk += KK) {
        __syncthreads();
        const float4* wg4 = (const float4*)(Wg1 + (size_t)kk * HIDN);
        float4* wt4 = (float4*)s_wt;            // 2048 float4s
#pragma unroll
        for (int i = 0; i < 4; i++) wt4[tid + i * NTHREADS] = wg4[tid + i * NTHREADS];
        __syncthreads();
#pragma unroll
        for (int k = 0; k < KK; k++) {
            ulonglong2 wv = *(const ulonglong2*)&s_wt[(size_t)k * HIDN + j0];
#pragma unroll
            for (int i = 0; i < 8; i++) {
                unsigned long long a2 = splat2(s_cand[(size_t)(r0 + i) * HDIM + kk + k]);
                ffma2(acc[i][0], a2, wv.x);
                ffma2(acc[i][1], a2, wv.y);
            }
        }
    }

    // epilogue layer 1: + base1, relu, store h1 tile
    {
        float4 bs = *(const float4*)&s_base[j0];
#pragma unroll
        for (int i = 0; i < 8; i++) {
            float2 a0 = unpack2(acc[i][0]);
            float2 a1 = unpack2(acc[i][1]);
            float4 h;
            h.x = fmaxf(a0.x + bs.x, 0.0f);
            h.y = fmaxf(a0.y + bs.y, 0.0f);
            h.z = fmaxf(a1.x + bs.z, 0.0f);
            h.w = fmaxf(a1.y + bs.w, 0.0f);
            *(float4*)&s_h1[(size_t)(r0 + i) * HIDN + j0] = h;
            acc[i][0] = 0ull; acc[i][1] = 0ull;
        }
    }

    // ---- layer 2: K = 512 ----
    for (int kk = 0; kk < HIDN; kk += KK) {
        __syncthreads();   // also guards the h1 writes above on first iter
        const float4* wg4 = (const float4*)(W2 + (size_t)kk * HIDN);
        float4* wt4 = (float4*)s_wt;
#pragma unroll
        for (int i = 0; i < 4; i++) wt4[tid + i * NTHREADS] = wg4[tid + i * NTHREADS];
        __syncthreads();
#pragma unroll
        for (int k = 0; k < KK; k++) {
            ulonglong2 wv = *(const ulonglong2*)&s_wt[(size_t)k * HIDN + j0];
#pragma unroll
            for (int i = 0; i < 8; i++) {
                unsigned long long a2 = splat2(s_h1[(size_t)(r0 + i) * HIDN + kk + k]);
                ffma2(acc[i][0], a2, wv.x);
                ffma2(acc[i][1], a2, wv.y);
            }
        }
    }

    // epilogue layer 2 + layer 3: relu(+b2), dot with W3, reduce per row
    {
        float4 b2v = *(const float4*)&b2[j0];
        float4 w3v = *(const float4*)&W3[j0];
#pragma unroll
        for (int i = 0; i < 8; i++) {
            float2 a0 = unpack2(acc[i][0]);
            float2 a1 = unpack2(acc[i][1]);
            float h0 = fmaxf(a0.x + b2v.x, 0.0f);
            float h1 = fmaxf(a0.y + b2v.y, 0.0f);
            float h2 = fmaxf(a1.x + b2v.z, 0.0f);
            float h3 = fmaxf(a1.y + b2v.w, 0.0f);
            float sc = h0 * w3v.x + h1 * w3v.y + h2 * w3v.z + h3 * w3v.w;
#pragma unroll
            for (int o = 16; o > 0; o >>= 1)
                sc += __shfl_xor_sync(0xffffffffu, sc, o);
            if ((tid & 31) == 0) atomicAdd(&s_score[r0 + i], sc);
        }
    }

    __syncthreads();
    if (tid < TM) {
        int d   = d0 + tid;
        int lim = ncnt[b] - 1;
        float v = (d < lim) ? (s_score[tid] + b3[0]) : NEGV;
        g_scores[(size_t)b * NMAXN + d] = v;   // 16 tiles * 32 = all 512 slots
    }
}

// ============================================================================
// Kernel 2: per-batch log-softmax NLL.  loss = max + log(sum exp) - score[dest]
// ============================================================================
__global__ void __launch_bounds__(NMAXN) loss_kernel(
    const int* __restrict__ dests, float* __restrict__ out)
{
    int b   = blockIdx.x;
    int tid = threadIdx.x;   // 512
    __shared__ float red[NMAXN];

    float v = g_scores[(size_t)b * NMAXN + tid];

    red[tid] = v;
    __syncthreads();
    for (int o = 256; o > 0; o >>= 1) {
        if (tid < o) red[tid] = fmaxf(red[tid], red[tid + o]);
        __syncthreads();
    }
    float mx = red[0];
    __syncthreads();

    red[tid] = expf(v - mx);
    __syncthreads();
    for (int o = 256; o > 0; o >>= 1) {
        if (tid < o) red[tid] = red[tid] + red[tid + o];
        __syncthreads();
    }

    if (tid == 0) {
        float sd = g_scores[(size_t)b * NMAXN + dests[b]];
        out[b] = mx + logf(red[0]) - sd;
    }
}

// ============================================================================
extern "C" void kernel_launch(void* const* d_in, const int* in_sizes, int n_in,
                              void* d_out, int out_size)
{
    const float* nodes = (const float*)d_in[0];
    const float* cc    = (const float*)d_in[1];
    const float* W1    = (const float*)d_in[2];
    const float* b1    = (const float*)d_in[3];
    const float* W2    = (const float*)d_in[4];
    const float* b2    = (const float*)d_in[5];
    const float* W3    = (const float*)d_in[6];
    const float* b3    = (const float*)d_in[7];
    const int* dirns   = (const int*)d_in[8];
    const int* ncnt    = (const int*)d_in[9];
    const int* dests   = (const int*)d_in[10];
    float* out = (float*)d_out;

    base_kernel<<<BATCH, HIDN>>>(nodes, cc, W1, b1, dirns, ncnt);

    size_t smem = (size_t)(TM * HDIM + TM * HIDN + KK * HIDN + HIDN + TM) * sizeof(float);
    cudaFuncSetAttribute(mlp_kernel, cudaFuncAttributeMaxDynamicSharedMemorySize, (int)smem);
    dim3 grid(NMAXN / TM, BATCH);   // 16 x 256
    mlp_kernel<<<grid, NTHREADS, smem>>>(nodes, W1, W2, b2, W3, b3, dirns, ncnt);

    loss_kernel<<<BATCH, NMAXN>>>(dests, out);
}

// round 14
// speedup vs baseline: 2.0822x; 2.0813x over previous
#include <cuda_runtime.h>
#include <cuda_bf16.h>
#include <cstdint>

#define BATCH   256
#define NMAXN   512
#define HDIM    256
#define CDIM    64
#define HIDN    512
#define NEGV   (-1000000000.0f)

// ---------------- device scratch (no allocations allowed) ----------------
__device__ float g_base1[BATCH * HIDN];
__device__ float g_scores[BATCH * NMAXN];
__device__ __align__(16) __nv_bfloat16 g_W1h[2][HIDN][HDIM];   // [side][n][k]
__device__ __align__(16) __nv_bfloat16 g_W1l[2][HIDN][HDIM];
__device__ __align__(16) __nv_bfloat16 g_W2h[HIDN][HIDN];      // [n][k]
__device__ __align__(16) __nv_bfloat16 g_W2l[HIDN][HIDN];

// ---------------- smem region offsets (from 1024-aligned base) ----------
// A:  64 rows x 256 k bf16, SW128 planes of 64x128B: hi 4*8192, lo +32768
// h1: 64 rows x 512 n bf16: hi 8*8192 @65536, lo @131072
// W slice buffer: 128 n x 32 k: hi 8192 @196608, lo @204800
#define OFF_AH   0u
#define OFF_AL   32768u
#define OFF_H1H  65536u
#define OFF_H1L  131072u
#define OFF_WB   196608u
#define DYN_SMEM (212992 + 1024)

#define SWZ(o)   ((o) ^ (((o) >> 3) & 0x70))
#define SWZ64(o) ((o) ^ (((o) >> 3) & 0x30))

// ---------------- helpers ----------------
__device__ __forceinline__ uint32_t smem_u32(const void* p) {
    uint32_t a;
    asm("{ .reg .u64 t; cvta.to.shared.u64 t, %1; cvt.u32.u64 %0, t; }" : "=r"(a) : "l"(p));
    return a;
}
// pack: x0 -> low 16 bits, x1 -> high 16 bits
__device__ __forceinline__ uint32_t bf2(float x0, float x1) {
    uint32_t r;
    asm("cvt.rn.bf16x2.f32 %0, %1, %2;" : "=r"(r) : "f"(x1), "f"(x0));
    return r;
}
__device__ __forceinline__ float lo_of(uint32_t u) { return __uint_as_float(u << 16); }
__device__ __forceinline__ float hi_of(uint32_t u) { return __uint_as_float(u & 0xffff0000u); }

__device__ __forceinline__ void sts128(uint32_t a, uint4 v) {
    asm volatile("st.shared.v4.b32 [%0], {%1,%2,%3,%4};"
                 :: "r"(a), "r"(v.x), "r"(v.y), "r"(v.z), "r"(v.w) : "memory");
}
__device__ __forceinline__ void sts64v2(uint32_t a, uint32_t x, uint32_t y) {
    asm volatile("st.shared.v2.b32 [%0], {%1,%2};" :: "r"(a), "r"(x), "r"(y) : "memory");
}
__device__ __forceinline__ void sts32(uint32_t a, uint32_t v) {
    asm volatile("st.shared.b32 [%0], %1;" :: "r"(a), "r"(v) : "memory");
}
__device__ __forceinline__ void ldsm4(uint32_t* r, uint32_t addr) {
    asm volatile("ldmatrix.sync.aligned.m8n8.x4.shared.b16 {%0,%1,%2,%3}, [%4];"
                 : "=r"(r[0]), "=r"(r[1]), "=r"(r[2]), "=r"(r[3]) : "r"(addr));
}
__device__ __forceinline__ void mma16816(float* c, const uint32_t* a, const uint32_t* b) {
    asm volatile("mma.sync.aligned.m16n8k16.row.col.f32.bf16.bf16.f32 "
                 "{%0,%1,%2,%3}, {%4,%5,%6,%7}, {%8,%9}, {%0,%1,%2,%3};"
                 : "+f"(c[0]), "+f"(c[1]), "+f"(c[2]), "+f"(c[3])
                 : "r"(a[0]), "r"(a[1]), "r"(a[2]), "r"(a[3]), "r"(b[0]), "r"(b[1]));
}

// unit t (0..95): t<32 -> layer1 (nc=t/8, ks=t%8); else layer2 (nc=(t-32)/16, ks=(t-32)%16)
__device__ __forceinline__ void unit_ptr(int t, int vs,
        const __nv_bfloat16*& hp, const __nv_bfloat16*& lp, int& pitch) {
    if (t < 32) {
        int nc = t >> 3, ks = t & 7;
        hp = &g_W1h[vs][nc * 128][ks * 32];
        lp = &g_W1l[vs][nc * 128][ks * 32];
        pitch = HDIM;
    } else {
        int u = t - 32, nc = u >> 4, ks = u & 15;
        hp = &g_W2h[nc * 128][ks * 32];
        lp = &g_W2l[nc * 128][ks * 32];
        pitch = HIDN;
    }
}
__device__ __forceinline__ void ldg_unit(uint4* R, const __nv_bfloat16* hp,
        const __nv_bfloat16* lp, int pitch, int tid) {
#pragma unroll
    for (int i = 0; i < 2; i++) {
        int idx = tid + i * 256;            // 512 uint4 per hi/lo
        int n = idx >> 2, kq = idx & 3;
        R[i]     = *(const uint4*)(hp + (size_t)n * pitch + kq * 8);
        R[2 + i] = *(const uint4*)(lp + (size_t)n * pitch + kq * 8);
    }
}
__device__ __forceinline__ void sts_unit(uint32_t sbase, const uint4* R, int tid) {
#pragma unroll
    for (int i = 0; i < 2; i++) {
        int idx = tid + i * 256;
        uint32_t n = (uint32_t)(idx >> 2), kq = (uint32_t)(idx & 3);
        uint32_t o = SWZ64(n * 64u + kq * 16u);
        sts128(sbase + OFF_WB + o, R[i]);
        sts128(sbase + OFF_WB + 8192u + o, R[2 + i]);
    }
}

// ============================================================================
// pack: transpose + hi/lo bf16 split of W1 sides and W2 into [n][k] scratch
// ============================================================================
__global__ void __launch_bounds__(256) pack_kernel(
    const float* __restrict__ W1, const float* __restrict__ W2)
{
    __shared__ float t[32][33];
    int z = blockIdx.z;
    int K = (z < 2) ? HDIM : HIDN;
    int kt = blockIdx.x * 32, nt = blockIdx.y * 32;
    if (kt >= K) return;
    const float* in = (z < 2) ? (W1 + (size_t)z * HDIM * HIDN) : W2;   // [K][512]
    __nv_bfloat16* oh = (z < 2) ? &g_W1h[z][0][0] : &g_W2h[0][0];
    __nv_bfloat16* ol = (z < 2) ? &g_W1l[z][0][0] : &g_W2l[0][0];
    int tx = threadIdx.x, ty = threadIdx.y;
#pragma unroll
    for (int i = 0; i < 4; i++)
        t[ty + 8 * i][tx] = in[(size_t)(kt + ty + 8 * i) * HIDN + nt + tx];
    __syncthreads();
#pragma unroll
    for (int i = 0; i < 4; i++) {
        int n = nt + ty + 8 * i, k = kt + tx;
        float x = t[tx][ty + 8 * i];
        __nv_bfloat16 h = __float2bfloat16(x);
        __nv_bfloat16 l = __float2bfloat16(x - __bfloat162float(h));
        oh[(size_t)n * K + k] = h;
        ol[(size_t)n * K + k] = l;
    }
}

// ============================================================================
// per-batch constant layer-1 contribution (exact fp32)
// ============================================================================
__global__ void __launch_bounds__(HIDN) base_kernel(
    const float* __restrict__ nodes, const float* __restrict__ cc,
    const float* __restrict__ W1, const float* __restrict__ b1,
    const int* __restrict__ dirns, const int* __restrict__ ncnt)
{
    int b = blockIdx.x, tid = threadIdx.x;
    __shared__ float s_src[HDIM];
    __shared__ float s_cc[CDIM];
    int si = ncnt[b] - 1;
    if (tid < HDIM) s_src[tid] = nodes[((size_t)b * NMAXN + si) * HDIM + tid];
    if (tid < CDIM) s_cc[tid]  = cc[(size_t)b * CDIM + tid];
    __syncthreads();
    int coff = (dirns[b] == 1) ? HDIM : 0;
    float acc = b1[tid];
    const float* Wc = W1 + (size_t)coff * HIDN + tid;
#pragma unroll 8
    for (int k = 0; k < HDIM; k++) acc += s_src[k] * Wc[(size_t)k * HIDN];
    const float* Wcc = W1 + (size_t)(2 * HDIM) * HIDN + tid;
#pragma unroll 8
    for (int k = 0; k < CDIM; k++) acc += s_cc[k] * Wcc[(size_t)k * HIDN];
    g_base1[(size_t)b * HIDN + tid] = acc;
}

// ============================================================================
// main fused MLP: mma.sync compensated bf16.  grid (8,256), 256 threads.
// ============================================================================
__global__ void __launch_bounds__(256, 1) mlp_kernel(
    const float* __restrict__ nodes,
    const float* __restrict__ b2g, const float* __restrict__ W3,
    const float* __restrict__ b3,
    const int* __restrict__ dirns, const int* __restrict__ ncnt)
{
    extern __shared__ char dynsm[];
    uint32_t sbase = (smem_u32(dynsm) + 1023u) & ~1023u;

    __shared__ float s_base[128];
    __shared__ float s_b2[128], s_w3[128];
    __shared__ float s_score[64];

    int b    = blockIdx.y;
    int d0   = blockIdx.x * 64;
    int tid  = threadIdx.x;
    int lane = tid & 31;
    int w    = tid >> 5;
    int wm   = w >> 2;      // 0..1  -> rows [wm*32, +32)
    int wn   = w & 3;       // 0..3  -> cols [wn*32, +32) within 128-chunk

    if (tid < 64) s_score[tid] = 0.0f;

    // ---- A tile: 64 rows x 256 k, fp32 -> bf16 hi/lo, SW128 K-major ----
    {
        const float* Ag = nodes + ((size_t)b * NMAXN + d0) * HDIM;
#pragma unroll
        for (int i = 0; i < 16; i++) {
            int g = tid + i * 256;              // 4096 float4
            int row = g >> 6, k4 = (g & 63) * 4;
            float4 v = *(const float4*)(Ag + (size_t)row * HDIM + k4);
            uint32_t h0 = bf2(v.x, v.y), h1 = bf2(v.z, v.w);
            uint32_t l0 = bf2(v.x - lo_of(h0), v.y - hi_of(h0));
            uint32_t l1 = bf2(v.z - lo_of(h1), v.w - hi_of(h1));
            uint32_t off = (uint32_t)(k4 >> 6) * 8192u
                         + SWZ((uint32_t)row * 128u + (uint32_t)(k4 & 63) * 2u);
            sts64v2(sbase + OFF_AH + off, h0, h1);
            sts64v2(sbase + OFF_AL + off, l0, l1);
        }
    }
    int vs = (dirns[b] == 1) ? 0 : 1;

    float acc[2][4][4];
#pragma unroll
    for (int mt = 0; mt < 2; mt++)
#pragma unroll
        for (int nt = 0; nt < 4; nt++)
#pragma unroll
            for (int q = 0; q < 4; q++) acc[mt][nt][q] = 0.0f;

    uint4 R[4];
    {
        const __nv_bfloat16 *hp, *lp; int pitch;
        unit_ptr(0, vs, hp, lp, pitch);
        ldg_unit(R, hp, lp, pitch, tid);
    }

    for (int t = 0; t < 96; t++) {
        __syncthreads();                       // W buffer free (prev compute done)
        sts_unit(sbase, R, tid);
        // chunk-start constant loads (prev epilogue finished before sync above)
        if (t < 32) {
            if ((t & 7) == 0 && tid < 128)
                s_base[tid] = g_base1[(size_t)b * HIDN + (t >> 3) * 128 + tid];
        } else {
            int u = t - 32;
            if ((u & 15) == 0 && tid < 128) {
                int nc = u >> 4;
                s_b2[tid] = b2g[nc * 128 + tid];
                s_w3[tid] = W3[nc * 128 + tid];
            }
        }
        __syncthreads();                       // W slice + constants visible
        if (t + 1 < 96) {
            const __nv_bfloat16 *hp, *lp; int pitch;
            unit_ptr(t + 1, vs, hp, lp, pitch);
            ldg_unit(R, hp, lp, pitch, tid);   // overlap with compute below
        }

        // ---- compute: 2 ksteps of 16 within this 32-k slice ----
        uint32_t abase = (t < 32) ? OFF_AH : OFF_H1H;
        uint32_t albas = (t < 32) ? OFF_AL : OFF_H1L;
        int kg0 = (t < 32) ? (t & 7) * 32 : ((t - 32) & 15) * 32;
#pragma unroll
        for (int ks2 = 0; ks2 < 32; ks2 += 16) {
            int kk = kg0 + ks2 + ((lane >> 4) << 3);     // A k coord for this lane
            uint32_t Ah[2][4], Al[2][4];
#pragma unroll
            for (int mt = 0; mt < 2; mt++) {
                uint32_t row = (uint32_t)(wm * 32 + mt * 16 + (lane & 15));
                uint32_t ao = (uint32_t)(kk >> 6) * 8192u
                            + SWZ(row * 128u + (uint32_t)(kk & 63) * 2u);
                ldsm4(Ah[mt], sbase + abase + ao);
                ldsm4(Al[mt], sbase + albas + ao);
            }
            uint32_t Bh[4][2], Bl[4][2];
#pragma unroll
            for (int np = 0; np < 2; np++) {
                uint32_t nl = (uint32_t)(wn * 32 + np * 16 + (lane & 7) + ((lane >> 4) << 3));
                uint32_t kb = (uint32_t)(ks2 + (((lane >> 3) & 1) << 3));
                uint32_t bo = SWZ64(nl * 64u + kb * 2u);
                uint32_t r[4];
                ldsm4(r, sbase + OFF_WB + bo);
                Bh[np * 2][0] = r[0]; Bh[np * 2][1] = r[1];
                Bh[np * 2 + 1][0] = r[2]; Bh[np * 2 + 1][1] = r[3];
                ldsm4(r, sbase + OFF_WB + 8192u + bo);
                Bl[np * 2][0] = r[0]; Bl[np * 2][1] = r[1];
                Bl[np * 2 + 1][0] = r[2]; Bl[np * 2 + 1][1] = r[3];
            }
#pragma unroll
            for (int mt = 0; mt < 2; mt++)
#pragma unroll
                for (int nt = 0; nt < 4; nt++) {
                    mma16816(acc[mt][nt], Ah[mt], Bh[nt]);
                    mma16816(acc[mt][nt], Al[mt], Bh[nt]);
                    mma16816(acc[mt][nt], Ah[mt], Bl[nt]);
                }
        }

        // ---- epilogues at chunk boundaries ----
        bool ep1 = (t < 32) && ((t & 7) == 7);
        bool ep2 = (t >= 32) && (((t - 32) & 15) == 15);
        if (ep1) {
            int nc = t >> 3;
#pragma unroll
            for (int mt = 0; mt < 2; mt++)
#pragma unroll
                for (int nt = 0; nt < 4; nt++)
#pragma unroll
                    for (int rh = 0; rh < 2; rh++) {
                        uint32_t row = (uint32_t)(wm * 32 + mt * 16 + (lane >> 2) + rh * 8);
                        int nl = wn * 32 + nt * 8 + 2 * (lane & 3);
                        float f0 = fmaxf(acc[mt][nt][rh * 2]     + s_base[nl],     0.0f);
                        float f1 = fmaxf(acc[mt][nt][rh * 2 + 1] + s_base[nl + 1], 0.0f);
                        uint32_t h = bf2(f0, f1);
                        uint32_t l = bf2(f0 - lo_of(h), f1 - hi_of(h));
                        int ng = nc * 128 + nl;
                        uint32_t off = (uint32_t)(ng >> 6) * 8192u
                                     + SWZ(row * 128u + (uint32_t)(ng & 63) * 2u);
                        sts32(sbase + OFF_H1H + off, h);
                        sts32(sbase + OFF_H1L + off, l);
                    }
        }
        if (ep2) {
#pragma unroll
            for (int mt = 0; mt < 2; mt++)
#pragma unroll
                for (int rh = 0; rh < 2; rh++) {
                    float rs = 0.0f;
#pragma unroll
                    for (int nt = 0; nt < 4; nt++) {
                        int nl = wn * 32 + nt * 8 + 2 * (lane & 3);
                        rs += fmaxf(acc[mt][nt][rh * 2]     + s_b2[nl],     0.0f) * s_w3[nl];
                        rs += fmaxf(acc[mt][nt][rh * 2 + 1] + s_b2[nl + 1], 0.0f) * s_w3[nl + 1];
                    }
                    rs += __shfl_xor_sync(0xffffffffu, rs, 1);
                    rs += __shfl_xor_sync(0xffffffffu, rs, 2);
                    if ((lane & 3) == 0)
                        atomicAdd(&s_score[wm * 32 + mt * 16 + (lane >> 2) + rh * 8], rs);
                }
        }
        if (ep1 || ep2) {
#pragma unroll
            for (int mt = 0; mt < 2; mt++)
#pragma unroll
                for (int nt = 0; nt < 4; nt++)
#pragma unroll
                    for (int q = 0; q < 4; q++) acc[mt][nt][q] = 0.0f;
        }
    }

    __syncthreads();
    if (tid < 64) {
        int lim = ncnt[b] - 1;
        int d = d0 + tid;
        g_scores[(size_t)b * NMAXN + d] = (d < lim) ? (s_score[tid] + b3[0]) : NEGV;
    }
}

// ============================================================================
// per-batch log-softmax NLL
// ============================================================================
__global__ void __launch_bounds__(NMAXN) loss_kernel(
    const int* __restrict__ dests, float* __restrict__ out)
{
    int b = blockIdx.x, tid = threadIdx.x;
    __shared__ float red[NMAXN];
    float v = g_scores[(size_t)b * NMAXN + tid];
    red[tid] = v;
    __syncthreads();
    for (int o = 256; o > 0; o >>= 1) {
        if (tid < o) red[tid] = fmaxf(red[tid], red[tid + o]);
        __syncthreads();
    }
    float mx = red[0];
    __syncthreads();
    red[tid] = expf(v - mx);
    __syncthreads();
    for (int o = 256; o > 0; o >>= 1) {
        if (tid < o) red[tid] = red[tid] + red[tid + o];
        __syncthreads();
    }
    if (tid == 0) {
        float sd = g_scores[(size_t)b * NMAXN + dests[b]];
        out[b] = mx + logf(red[0]) - sd;
    }
}

// ============================================================================
extern "C" void kernel_launch(void* const* d_in, const int* in_sizes, int n_in,
                              void* d_out, int out_size)
{
    const float* nodes = (const float*)d_in[0];
    const float* cc    = (const float*)d_in[1];
    const float* W1    = (const float*)d_in[2];
    const float* b1    = (const float*)d_in[3];
    const float* W2    = (const float*)d_in[4];
    const float* b2    = (const float*)d_in[5];
    const float* W3    = (const float*)d_in[6];
    const float* b3    = (const float*)d_in[7];
    const int* dirns   = (const int*)d_in[8];
    const int* ncnt    = (const int*)d_in[9];
    const int* dests   = (const int*)d_in[10];
    float* out = (float*)d_out;

    dim3 pg(16, 16, 3), pb(32, 8);
    pack_kernel<<<pg, pb>>>(W1, W2);

    base_kernel<<<BATCH, HIDN>>>(nodes, cc, W1, b1, dirns, ncnt);

    cudaFuncSetAttribute(mlp_kernel, cudaFuncAttributeMaxDynamicSharedMemorySize, DYN_SMEM);
    dim3 grid(8, BATCH);
    mlp_kernel<<<grid, 256, DYN_SMEM>>>(nodes, b2, W3, b3, dirns, ncnt);

    loss_kernel<<<BATCH, NMAXN>>>(dests, out);
}